// round 3
// baseline (speedup 1.0000x reference)
#include <cuda_runtime.h>

// Problem: x (1,128,56,56) f32, W (32,64,3) f32 -> out (1,32,56,56) f32
//   t2[c,h,w]   = x[c,h,w] + x[c+64,h,w]                       (channel-pair sum)
//   out[i,h,w]  = sum_{c<64,k<3} t2[c, h+k-1, w] * W[i,c,k]    (3-tap conv along H, zero pad)
//   result[i,h,w] = out[i,h,(w-1) mod 56]  == store out(w) at (w+1)%56   (roll +1)

#define TILE_W 14
#define C64    64
#define CPAD   68   // 64 + 4 pad: w-stride 272B -> 16B bank-quad shift per lane, conflict-light LDS.128

__global__ __launch_bounds__(448, 4)
void fused_pairconv_roll(const float* __restrict__ x,
                         const float* __restrict__ W,
                         float* __restrict__ out)
{
    __shared__ __align__(16) float sh_t2[3 * TILE_W * CPAD];   // [k][w][c]  ~11.2 KB
    __shared__ __align__(16) float sh_W [32 * 3 * CPAD];       // [i][k][c]  ~26.1 KB

    const int h   = blockIdx.y;            // 0..55
    const int w0  = blockIdx.x * TILE_W;   // 0,14,28,42
    const int tid = threadIdx.x + threadIdx.y * TILE_W;  // 0..447

    // ---- stage t2 taps into shared: sh_t2[k][w][c] = t2[c, h-1+k, w0+w] (zero-padded in h)
    //      2688 elements / 448 threads = exactly 6 iterations
    #pragma unroll
    for (int it = 0; it < 6; ++it) {
        int idx = tid + it * 448;
        int w = idx % TILE_W;
        int c = (idx / TILE_W) % C64;
        int k = idx / (TILE_W * C64);
        int row = h - 1 + k;
        float v = 0.0f;
        if (row >= 0 && row < 56) {
            int base = row * 56 + (w0 + w);
            v = x[c * 3136 + base] + x[(c + 64) * 3136 + base];
        }
        sh_t2[(k * TILE_W + w) * CPAD + c] = v;
    }

    // ---- stage W transposed: sh_W[i][k][c] = W[i,c,k]   (6144 elements)
    for (int idx = tid; idx < 32 * 3 * C64; idx += 448) {
        int c = idx % C64;
        int k = (idx / C64) % 3;
        int i = idx / (3 * C64);
        sh_W[(i * 3 + k) * CPAD + c] = W[(i * C64 + c) * 3 + k];
    }
    __syncthreads();

    // ---- one output per thread: (i = threadIdx.y, h, w = w0 + threadIdx.x)
    const int tx = threadIdx.x;
    const int i  = threadIdx.y;

    float a0 = 0.f, a1 = 0.f, a2 = 0.f, a3 = 0.f;
    #pragma unroll
    for (int k = 0; k < 3; ++k) {
        const float4* __restrict__ t2p = (const float4*)&sh_t2[(k * TILE_W + tx) * CPAD];
        const float4* __restrict__ wp  = (const float4*)&sh_W [(i * 3      + k ) * CPAD];
        #pragma unroll
        for (int c4 = 0; c4 < C64 / 4; ++c4) {
            float4 a = t2p[c4];
            float4 b = wp[c4];
            a0 = fmaf(a.x, b.x, a0);
            a1 = fmaf(a.y, b.y, a1);
            a2 = fmaf(a.z, b.z, a2);
            a3 = fmaf(a.w, b.w, a3);
        }
    }
    float r = (a0 + a1) + (a2 + a3);

    const int w    = w0 + tx;
    const int wout = (w + 1 < 56) ? (w + 1) : 0;   // roll shift = +1 along width
    out[i * 3136 + h * 56 + wout] = r;
}

extern "C" void kernel_launch(void* const* d_in, const int* in_sizes, int n_in,
                              void* d_out, int out_size)
{
    // Resolve inputs by size (defensive: x = 128*56*56 = 401408, W = 32*64*3 = 6144)
    const float* x = (const float*)d_in[0];
    const float* W = (const float*)d_in[1];
    if (n_in >= 2 && in_sizes[0] == 6144 && in_sizes[1] == 401408) {
        x = (const float*)d_in[1];
        W = (const float*)d_in[0];
    }
    float* out = (float*)d_out;   // 32*56*56 = 100352

    dim3 grid(56 / TILE_W, 56);   // (4, 56) = 224 blocks, single wave on 148 SMs
    dim3 block(TILE_W, 32);       // 448 threads
    fused_pairconv_roll<<<grid, block>>>(x, W, out);
}

// round 6
// speedup vs baseline: 1.1633x; 1.1633x over previous
#include <cuda_runtime.h>

// x (1,128,56,56) f32, W (32,64,3) f32 -> out (1,32,56,56) f32
//   t2[c,h,w]  = x[c,h,w] + x[c+64,h,w]
//   out[i,h,w] = sum_{c,k} t2[c, h+k-1, w] * W[i,c,k]   (3-tap H conv, zero pad)
//   store rolled +1 along w.
//
// Key layout trick: W row i is natively ordered j = c*3+k. Stage taps as
// t3[w][j] = t2[c(j), h-1+k(j), w] so BOTH main-loop operands are contiguous
// float4 in native order. W staging = pure coalesced float4 copy, no transpose.

#define TILE_W 7
#define RLEN   192          // 64 c * 3 k
#define RPAD   196          // row stride: 784B -> ty/tx strides land 4 banks apart, conflict-light
#define NTHR   224          // 7 x 32

__global__ __launch_bounds__(NTHR, 3)
void fused_pairconv_roll(const float* __restrict__ x,
                         const float* __restrict__ W,
                         float* __restrict__ out)
{
    __shared__ __align__(16) float sh_t3[TILE_W * RPAD];   // [w][j]  5.5 KB
    __shared__ __align__(16) float sh_W [32 * RPAD];       // [i][j] 25.1 KB

    const int h   = blockIdx.y;             // 0..55
    const int w0  = blockIdx.x * TILE_W;    // 0,7,...,49
    const int tx  = threadIdx.x;            // w within tile (7)
    const int ty  = threadIdx.y;            // i (32)
    const int tid = tx + ty * TILE_W;       // 0..223

    // ---- stage W: straight float4 copy, native order (1536 float4, 7 iters)
    {
        const float4* __restrict__ Wf4 = (const float4*)W;
        #pragma unroll
        for (int it = 0; it < 7; ++it) {
            int idx = tid + it * NTHR;          // < 1536
            if (idx < 1536) {
                int i  = idx / 48;              // const-div, cheap
                int jj = idx - i * 48;
                ((float4*)sh_W)[i * (RPAD / 4) + jj] = Wf4[idx];
            }
        }
    }

    // ---- stage taps: sh_t3[tx][j] = t2[c, h-1+k, w0+tx],  j = c*3+k
    //      192 j-values per w; thread (tx,ty) covers j = ty + 32*it, 6 iters exact
    #pragma unroll
    for (int it = 0; it < 6; ++it) {
        int j   = ty + 32 * it;                 // 0..191
        int c   = j / 3;                        // const-div
        int k   = j - 3 * c;
        int row = h - 1 + k;
        float v = 0.0f;
        if (row >= 0 && row < 56) {
            int base = row * 56 + (w0 + tx);
            v = x[c * 3136 + base] + x[(c + 64) * 3136 + base];
        }
        sh_t3[tx * RPAD + j] = v;
    }
    __syncthreads();

    // ---- one output per thread: (i = ty, h, w = w0 + tx)
    const float4* __restrict__ t3p = (const float4*)&sh_t3[tx * RPAD];
    const float4* __restrict__ wp  = (const float4*)&sh_W [ty * RPAD];

    float a0 = 0.f, a1 = 0.f, a2 = 0.f, a3 = 0.f;
    #pragma unroll
    for (int j4 = 0; j4 < RLEN / 4; ++j4) {     // 48 iters: 2x LDS.128 + 4 FFMA
        float4 a = t3p[j4];
        float4 b = wp[j4];
        a0 = fmaf(a.x, b.x, a0);
        a1 = fmaf(a.y, b.y, a1);
        a2 = fmaf(a.z, b.z, a2);
        a3 = fmaf(a.w, b.w, a3);
    }
    float r = (a0 + a1) + (a2 + a3);

    const int w    = w0 + tx;
    const int wout = (w + 1 < 56) ? (w + 1) : 0;   // roll +1 along width
    out[ty * 3136 + h * 56 + wout] = r;
}

extern "C" void kernel_launch(void* const* d_in, const int* in_sizes, int n_in,
                              void* d_out, int out_size)
{
    // Resolve inputs by size (x = 401408, W = 6144)
    const float* x = (const float*)d_in[0];
    const float* W = (const float*)d_in[1];
    if (n_in >= 2 && in_sizes[0] == 6144 && in_sizes[1] == 401408) {
        x = (const float*)d_in[1];
        W = (const float*)d_in[0];
    }
    float* out = (float*)d_out;

    dim3 grid(56 / TILE_W, 56);   // (8,56) = 448 CTAs -> 3.03/SM, balanced
    dim3 block(TILE_W, 32);       // 224 threads
    fused_pairconv_roll<<<grid, block>>>(x, W, out);
}